// round 13
// baseline (speedup 1.0000x reference)
#include <cuda_runtime.h>
#include <cuda_bf16.h>

// SNN dense (TTFS) — B=64, IN=1024 (+1 bias row), OUT=1024.
// SINGLE fused persistent kernel (grid 592 x 512):
//   tickets 0..63    : sort row b (stable rank-count, packed u64 keys)
//   tickets 64..1087 : scan item (b, 64-neuron block), spins on row-ready flag
//   tickets >=1088   : exit (exactly 592 per replay -> 1680 tickets/replay,
//                      so epoch = t/1680 needs no counter reset; deterministic)
// Scan math is bit-identical to R10 (packed f32x2 accumulate, clip+fast-div,
// select-min), with the select+min pair fused into setp/setp.or/@!p min.f32.

#define BATCH 64
#define IN_SZ 1024
#define KTOT 1025
#define OUT_SZ 1024
#define MAXT 100000.0f
#define EPSV 1e-10f
#define BIASV 1.0f

#define NW 16
#define CHUNK ((KTOT + NW - 1) / NW)       // 65
#define MBLK 64
#define NSORT BATCH                         // 64
#define NSCAN (BATCH * (OUT_SZ / MBLK))     // 1024
#define NWORK (NSORT + NSCAN)               // 1088
#define GRID_P 592
#define TPR (NWORK + GRID_P)                // 1680 tickets per replay

typedef unsigned long long ull;

__device__ __forceinline__ ull f2_add(ull a, ull b) {
    ull r; asm("add.rn.f32x2 %0,%1,%2;" : "=l"(r) : "l"(a), "l"(b)); return r;
}
__device__ __forceinline__ ull f2_fma(ull a, ull b, ull c) {
    ull r; asm("fma.rn.f32x2 %0,%1,%2,%3;" : "=l"(r) : "l"(a), "l"(b), "l"(c)); return r;
}
__device__ __forceinline__ ull f2_bcast(float x) {
    ull r; asm("mov.b64 %0,{%1,%1};" : "=l"(r) : "f"(x)); return r;
}
__device__ __forceinline__ void f2_unpack(float& lo, float& hi, ull v) {
    asm("mov.b64 {%0,%1},%2;" : "=f"(lo), "=f"(hi) : "l"(v));
}
// best = min(best, cand) iff cand in [x, nx]; predicated, no FSEL.
__device__ __forceinline__ void eval_min(float& best, float cand, float x, float nx) {
    asm("{\n\t.reg .pred p;\n\t"
        "setp.lt.f32 p, %1, %2;\n\t"
        "setp.gt.or.f32 p, %1, %3, p;\n\t"
        "@!p min.f32 %0, %0, %1;\n\t}"
        : "+f"(best) : "f"(cand), "f"(x), "f"(nx));
}

// Scratch (device globals; zero-init; no allocation allowed)
__device__ int2 g_pack[BATCH][KTOT + 1];
__device__ ull g_ticket;            // monotonically increasing across replays
__device__ unsigned g_ready[BATCH]; // row b ready when g_ready[b] >= epoch+1

struct SmemScan {
    int2  sp[KTOT + 1];
    ull   pw[NW][32];
    ull   pt[NW][32];
    float pm[NW][MBLK];
};
struct SmemSort { ull sk[KTOT + 1]; };   // 1026 keys incl. pad

__global__ void __launch_bounds__(512, 4) snn_fused_kernel(
        const float* __restrict__ X, const float* __restrict__ W,
        float* __restrict__ out) {
    __shared__ char raw[sizeof(SmemScan)];
    __shared__ ull s_t;

    const int tid  = threadIdx.x;
    const int w    = tid >> 5;
    const int lane = tid & 31;
    const int k0 = w * CHUNK;
    const int k1 = (k0 + CHUNK < KTOT) ? (k0 + CHUNK) : KTOT;
    const int k1m = (w == NW - 1) ? (KTOT - 1) : k1;

    for (;;) {
        if (tid == 0) s_t = atomicAdd(&g_ticket, 1ull);
        __syncthreads();
        const ull t = s_t;
        const unsigned epoch = (unsigned)(t / TPR);
        const unsigned id    = (unsigned)(t % TPR);
        if (id >= NWORK) return;

        if (id < NSORT) {
            // ================= SORT row b =================
            const int b = id;
            SmemSort& S = *reinterpret_cast<SmemSort*>(raw);
            for (int j = tid; j < KTOT; j += 512) {
                float v = (j < IN_SZ) ? X[b * IN_SZ + j] : BIASV;
                S.sk[j] = ((ull)__float_as_uint(v) << 32) | (unsigned)j;
            }
            if (tid == 0) {
                S.sk[KTOT] = ~0ull;                    // pad (never counted)
                int2 s; s.x = __float_as_int(MAXT); s.y = 0;
                g_pack[b][KTOT] = s;                   // next_x sentinel
            }
            __syncthreads();

            const ull ka = S.sk[tid];
            const ull kb = S.sk[tid + 512];
            const ull kc = S.sk[1024];                 // ranked by thread 0
            int ra = 0, rb = 0, rc = 0;
            const ulonglong2* p2 = reinterpret_cast<const ulonglong2*>(S.sk);
            #pragma unroll 4
            for (int j2 = 0; j2 < (KTOT + 1) / 2; ++j2) {
                ulonglong2 v = p2[j2];
                ra += (v.x < ka) + (v.y < ka);
                rb += (v.x < kb) + (v.y < kb);
                rc += (v.x < kc) + (v.y < kc);
            }
            int2 p;
            p.x = (int)(ka >> 32); p.y = ((int)(ka & 0xFFFFFFFFu)) * (OUT_SZ * 4);
            g_pack[b][ra] = p;
            p.x = (int)(kb >> 32); p.y = ((int)(kb & 0xFFFFFFFFu)) * (OUT_SZ * 4);
            g_pack[b][rb] = p;
            if (tid == 0) {
                p.x = (int)(kc >> 32); p.y = ((int)(kc & 0xFFFFFFFFu)) * (OUT_SZ * 4);
                g_pack[b][rc] = p;
            }
            __syncthreads();
            if (tid == 0) {
                __threadfence();                       // release
                *(volatile unsigned*)&g_ready[b] = epoch + 1;
            }
        } else {
            // ================= SCAN item =================
            const int it    = id - NSORT;
            const int b     = it >> 4;
            const int mbase = (it & 15) * MBLK;

            if (tid == 0) {
                while (*(volatile unsigned*)&g_ready[b] < epoch + 1)
                    __nanosleep(64);
            }
            __syncthreads();

            SmemScan& S = *reinterpret_cast<SmemScan*>(raw);
            for (int j = tid; j < KTOT + 1; j += 512)
                S.sp[j] = g_pack[b][j];
            __syncthreads();

            const char* Wb = (const char*)W + (size_t)(mbase + 2 * lane) * 4;

            // ---- pass 1 (warp 15's sums unused by anyone: skip) ----
            if (w < NW - 1) {
                ull s2 = 0ull, t2 = 0ull;
                #pragma unroll 4
                for (int k = k0; k < k1; ++k) {
                    const int2 pk = S.sp[k];
                    const ull w2 = *reinterpret_cast<const ull*>(Wb + pk.y);
                    s2 = f2_add(s2, w2);
                    t2 = f2_fma(w2, f2_bcast(__int_as_float(pk.x)), t2);
                }
                S.pw[w][lane] = s2;
                S.pt[w][lane] = t2;
            }
            __syncthreads();

            // ---- exclusive prefix (threshold folded: start at -1) ----
            ull cw2 = 0xBF800000BF800000ull;   // (-1.f, -1.f)
            ull ct2 = 0ull;
            for (int c = 0; c < w; ++c) {
                cw2 = f2_add(cw2, S.pw[c][lane]);
                ct2 = f2_add(ct2, S.pt[c][lane]);
            }

            // ---- pass 2 ----
            float best0 = MAXT, best1 = MAXT;
            int2 pc = S.sp[k0];
            #pragma unroll 4
            for (int k = k0; k < k1m; ++k) {
                const float x  = __int_as_float(pc.x);
                const int  off = pc.y;
                pc = S.sp[k + 1];
                const float nx = __int_as_float(pc.x);
                const ull w2 = *reinterpret_cast<const ull*>(Wb + off);

                cw2 = f2_add(cw2, w2);
                ct2 = f2_fma(w2, f2_bcast(x), ct2);
                float cw0, cw1, ct0, ct1;
                f2_unpack(cw0, cw1, cw2);
                f2_unpack(ct0, ct1, ct2);
                // cw<0 is inert here (den=EPS => cand outside [x,nx<=2])
                eval_min(best0, __fdividef(ct0, fmaxf(cw0, EPSV)), x, nx);
                eval_min(best1, __fdividef(ct1, fmaxf(cw1, EPSV)), x, nx);
            }
            if (w == NW - 1) {   // peeled final k: nx=MAXT, needs cw<0 check
                const float x  = __int_as_float(pc.x);
                const ull w2 = *reinterpret_cast<const ull*>(Wb + pc.y);
                cw2 = f2_add(cw2, w2);
                ct2 = f2_fma(w2, f2_bcast(x), ct2);
                float cw0, cw1, ct0, ct1;
                f2_unpack(cw0, cw1, cw2);
                f2_unpack(ct0, ct1, ct2);
                {
                    float cand = __fdividef(ct0, fmaxf(cw0, EPSV));
                    bool bad = (cw0 < 0.f) | (cand < x) | (cand > MAXT);
                    best0 = fminf(best0, bad ? MAXT : cand);
                }
                {
                    float cand = __fdividef(ct1, fmaxf(cw1, EPSV));
                    bool bad = (cw1 < 0.f) | (cand < x) | (cand > MAXT);
                    best1 = fminf(best1, bad ? MAXT : cand);
                }
            }
            S.pm[w][2 * lane]     = best0;
            S.pm[w][2 * lane + 1] = best1;
            __syncthreads();

            if (tid < MBLK) {
                float bb = MAXT;
                #pragma unroll
                for (int c = 0; c < NW; ++c)
                    bb = fminf(bb, S.pm[c][tid]);
                out[b * OUT_SZ + mbase + tid] = bb;
            }
        }
        __syncthreads();   // protect smem/s_t before next ticket
    }
}

// ---------------------------------------------------------------------------
extern "C" void kernel_launch(void* const* d_in, const int* in_sizes, int n_in,
                              void* d_out, int out_size) {
    const float* X = (const float*)d_in[0];
    const float* W = (const float*)d_in[1];
    if (n_in >= 2 && in_sizes[0] != BATCH * IN_SZ && in_sizes[1] == BATCH * IN_SZ) {
        X = (const float*)d_in[1];
        W = (const float*)d_in[0];
    }
    float* out = (float*)d_out;

    snn_fused_kernel<<<GRID_P, 512>>>(X, W, out);
}

// round 15
// speedup vs baseline: 1.3341x; 1.3341x over previous
#include <cuda_runtime.h>
#include <cuda_bf16.h>

// SNN dense (TTFS) — B=64, IN=1024 (+1 bias row), OUT=1024.
//   K1: stable rank-count sort, 4-way split of compare range (R10 proven).
//   K2: persistent work-stealing scan; 16 warps split k; packed f32x2
//       accumulators; DIVISION-FREE validity test (2 FFMA + setp chain),
//       divide only for valid candidates behind a warp-any branch.

#define BATCH 64
#define IN_SZ 1024
#define KTOT 1025          // IN_SZ + bias
#define OUT_SZ 1024
#define MAXT 100000.0f
#define BIASV 1.0f

#define NW 16              // warps (K-chunks) per item
#define CHUNK ((KTOT + NW - 1) / NW)   // 65
#define MBLK 64            // outputs per item (2 per lane)
#define NITEMS (BATCH * (OUT_SZ / MBLK))   // 1024
#define GRID_SCAN 592      // 148 SMs x 4 CTAs

#define SORT_ELEMS 64
#define SORT_PARTS 4
#define SORT_BLOCK (SORT_ELEMS * SORT_PARTS)   // 256
#define J2TOT ((KTOT + 1) / 2)                 // 513 ull2 chunks

typedef unsigned long long ull;

// packed f32x2 helpers (sm_103a FFMA2/FADD2 — only reachable via PTX)
__device__ __forceinline__ ull f2_add(ull a, ull b) {
    ull r; asm("add.rn.f32x2 %0,%1,%2;" : "=l"(r) : "l"(a), "l"(b)); return r;
}
__device__ __forceinline__ ull f2_fma(ull a, ull b, ull c) {
    ull r; asm("fma.rn.f32x2 %0,%1,%2,%3;" : "=l"(r) : "l"(a), "l"(b), "l"(c)); return r;
}
__device__ __forceinline__ ull f2_bcast(float x) {
    ull r; asm("mov.b64 %0,{%1,%1};" : "=l"(r) : "f"(x)); return r;
}
__device__ __forceinline__ void f2_unpack(float& lo, float& hi, ull v) {
    asm("mov.b64 {%0,%1},%2;" : "=f"(lo), "=f"(hi) : "l"(v));
}

// Scratch (device globals; no allocation allowed)
__device__ int2 g_pack[BATCH][KTOT + 1];  // {float bits of x, W byte offset}
__device__ unsigned g_ticket;

// ---------------------------------------------------------------------------
// Kernel 1: stable counting sort via packed u64 keys, 4-way range split.
// key = (float_bits << 32) | index — positive floats order as uints; index
// tie-break = exact jnp.argsort stability.
// ---------------------------------------------------------------------------
__global__ void __launch_bounds__(SORT_BLOCK) snn_sort_kernel(const float* __restrict__ X) {
    const int b = blockIdx.y;
    __shared__ ull sk[KTOT + 1];
    __shared__ int pr[SORT_ELEMS][SORT_PARTS];

    for (int j = threadIdx.x; j < KTOT; j += SORT_BLOCK) {
        float v = (j < IN_SZ) ? X[b * IN_SZ + j] : BIASV;
        sk[j] = ((ull)__float_as_uint(v) << 32) | (unsigned)j;
    }
    if (threadIdx.x == 0) {
        sk[KTOT] = ~0ull;
        if (blockIdx.x == 0 && b == 0) g_ticket = 0;
        int2 s; s.x = __float_as_int(MAXT); s.y = 0;
        if (blockIdx.x == 0) g_pack[b][KTOT] = s;      // next_x sentinel
    }
    __syncthreads();

    const int li   = threadIdx.x & (SORT_ELEMS - 1);
    const int part = threadIdx.x >> 6;
    const int i    = blockIdx.x * SORT_ELEMS + li;
    const bool valid = (i < KTOT);

    const ull ki = valid ? sk[i] : ~0ull;
    const int lo = (J2TOT * part) / SORT_PARTS;
    const int hi = (J2TOT * (part + 1)) / SORT_PARTS;

    int r = 0;
    const ulonglong2* sk2 = reinterpret_cast<const ulonglong2*>(sk);
    #pragma unroll 4
    for (int j2 = lo; j2 < hi; ++j2) {
        ulonglong2 v = sk2[j2];
        r += (v.x < ki);
        r += (v.y < ki);
    }
    pr[li][part] = r;
    __syncthreads();

    if (part == 0 && valid) {
        int rank = pr[li][0] + pr[li][1] + pr[li][2] + pr[li][3];
        int2 p;
        p.x = (int)(ki >> 32);
        p.y = ((int)(ki & 0xFFFFFFFFu)) * (OUT_SZ * 4);
        g_pack[b][rank] = p;
    }
}

// ---------------------------------------------------------------------------
// Kernel 2: persistent work-stealing scan. grid = 592, block = 512.
// Item = (b, m-block of 64). Warp w owns k in [w*CHUNK, ...); lane L owns
// outputs mbase + 2L, 2L+1. cw starts at -1 (threshold folded).
// Validity: cand = ct/cw in [x,nx] with cw>0  <=>  cw>0 & ct-x*cw>=0 &
// nx*cw-ct>=0  (no division; divide only when valid — rare).
// cw==0 / cw in (0,EPS) corner: reference clips den to 1e-10 giving a huge
// invalid candidate; our cw>0 / exact test agrees except on measure-zero.
// ---------------------------------------------------------------------------
__global__ void __launch_bounds__(512, 4) snn_scan_kernel(const float* __restrict__ W,
                                                          float* __restrict__ out) {
    __shared__ int2  sp[KTOT + 1];
    __shared__ ull   pw[NW][32];
    __shared__ ull   pt[NW][32];
    __shared__ float pm[NW][MBLK];
    __shared__ unsigned s_item;

    const int w    = threadIdx.x >> 5;
    const int lane = threadIdx.x & 31;
    const int k0 = w * CHUNK;
    const int k1 = (k0 + CHUNK < KTOT) ? (k0 + CHUNK) : KTOT;

    for (;;) {
        if (threadIdx.x == 0) s_item = atomicAdd(&g_ticket, 1u);
        __syncthreads();
        const unsigned item = s_item;
        if (item >= NITEMS) return;

        const int b     = item >> 4;
        const int mbase = (item & 15) * MBLK;

        for (int j = threadIdx.x; j < KTOT + 1; j += blockDim.x)
            sp[j] = g_pack[b][j];
        __syncthreads();

        const char* Wb = (const char*)W + (size_t)(mbase + 2 * lane) * 4;

        // ---- pass 1: packed chunk partial sums (warp 15's unused) ----
        if (w < NW - 1) {
            ull s2 = 0ull, t2 = 0ull;
            #pragma unroll 4
            for (int k = k0; k < k1; ++k) {
                const int2 p = sp[k];
                const ull w2 = *reinterpret_cast<const ull*>(Wb + p.y);
                s2 = f2_add(s2, w2);
                t2 = f2_fma(w2, f2_bcast(__int_as_float(p.x)), t2);
            }
            pw[w][lane] = s2;
            pt[w][lane] = t2;
        }
        __syncthreads();

        // ---- exclusive prefix (threshold folded: start at -1) ----
        ull cw2 = 0xBF800000BF800000ull;   // (-1.f, -1.f)
        ull ct2 = 0ull;
        for (int c = 0; c < w; ++c) {
            cw2 = f2_add(cw2, pw[c][lane]);
            ct2 = f2_add(ct2, pt[c][lane]);
        }

        // ---- pass 2: scan chunk, division-free validity ----
        float best0 = MAXT, best1 = MAXT;
        int2 pc = sp[k0];
        #pragma unroll 4
        for (int k = k0; k < k1; ++k) {
            const float x  = __int_as_float(pc.x);
            const int  off = pc.y;
            pc = sp[k + 1];
            const float nx = __int_as_float(pc.x);   // sentinel gives MAXT at k=KTOT-1
            const ull w2 = *reinterpret_cast<const ull*>(Wb + off);

            cw2 = f2_add(cw2, w2);
            ct2 = f2_fma(w2, f2_bcast(x), ct2);
            float cw0, cw1, ct0, ct1;
            f2_unpack(cw0, cw1, cw2);
            f2_unpack(ct0, ct1, ct2);

            const float a0 = fmaf(-x, cw0, ct0);     // ct - x*cw
            const float b0 = fmaf(nx, cw0, -ct0);    // nx*cw - ct
            const float a1 = fmaf(-x, cw1, ct1);
            const float b1 = fmaf(nx, cw1, -ct1);
            const bool v0 = (cw0 > 0.f) & (a0 >= 0.f) & (b0 >= 0.f);
            const bool v1 = (cw1 > 0.f) & (a1 >= 0.f) & (b1 >= 0.f);

            if (__any_sync(0xFFFFFFFFu, v0 | v1)) {  // rare (~12% of k)
                if (v0) best0 = fminf(best0, __fdividef(ct0, cw0));
                if (v1) best1 = fminf(best1, __fdividef(ct1, cw1));
            }
        }
        pm[w][2 * lane]     = best0;
        pm[w][2 * lane + 1] = best1;
        __syncthreads();

        // ---- final min across chunks ----
        if (threadIdx.x < MBLK) {
            float bb = MAXT;
            #pragma unroll
            for (int c = 0; c < NW; ++c)
                bb = fminf(bb, pm[c][threadIdx.x]);
            out[b * OUT_SZ + mbase + threadIdx.x] = bb;
        }
        __syncthreads();
    }
}

// ---------------------------------------------------------------------------
extern "C" void kernel_launch(void* const* d_in, const int* in_sizes, int n_in,
                              void* d_out, int out_size) {
    const float* X = (const float*)d_in[0];
    const float* W = (const float*)d_in[1];
    if (n_in >= 2 && in_sizes[0] != BATCH * IN_SZ && in_sizes[1] == BATCH * IN_SZ) {
        X = (const float*)d_in[1];
        W = (const float*)d_in[0];
    }
    float* out = (float*)d_out;

    dim3 gs((KTOT + SORT_ELEMS - 1) / SORT_ELEMS, BATCH);   // (17, 64)
    snn_sort_kernel<<<gs, SORT_BLOCK>>>(X);

    snn_scan_kernel<<<GRID_SCAN, 512>>>(W, out);
}